// round 7
// baseline (speedup 1.0000x reference)
#include <cuda_runtime.h>
#include <cuda_fp16.h>

#define N_NODES 100000
#define E_EDGES 1600000
#define IN_C    32
#define HID     32
#define OUT_C   8
#define EDGE_D  16
#define GRAPH_D 16

// ---------------- device scratch ----------------
__device__ float  g_hi [N_NODES * HID];
__device__ __half g_Prh[N_NODES * EDGE_D];  // fp16 P_r (+ bias + hG folded in)
__device__ __half g_Pch[N_NODES * EDGE_D];  // fp16 P_c
__device__ float  g_mN [N_NODES * EDGE_D];
__device__ float  g_h2 [N_NODES * HID];
__device__ float  g_t  [N_NODES];           // sum over out-edges of 1/ccnt[col]
__device__ float  g_rcnt[N_NODES];
__device__ float  g_ccnt[N_NODES];
__device__ float  g_hG [GRAPH_D];
__device__ float  g_S0 [HID];
__device__ float  g_S1 [HID];

__device__ __forceinline__ void red_add_f4(float* addr, float a, float b, float c, float d) {
    asm volatile("red.global.add.v4.f32 [%0], {%1,%2,%3,%4};"
                 :: "l"(addr), "f"(a), "f"(b), "f"(c), "f"(d) : "memory");
}

// ---------------- kernel 1: graph embedding + zero S0/S1 ----------------
__global__ void k_hG(const float* __restrict__ ga, const float* __restrict__ Wg,
                     const float* __restrict__ bg) {
    int j = threadIdx.x;
    if (j < GRAPH_D) {
        float acc = bg[j];
        #pragma unroll
        for (int k = 0; k < GRAPH_D; k++) acc += ga[k] * Wg[k * GRAPH_D + j];
        g_hG[j] = acc;
    }
    if (j < HID) { g_S0[j] = 0.f; g_S1[j] = 0.f; }
}

// ---------------- stream-B kernel A: zero degree arrays ----------------
__global__ void __launch_bounds__(256)
k_zeroDeg() {
    int n = blockIdx.x * blockDim.x + threadIdx.x;
    if (n < N_NODES) { g_rcnt[n] = 0.f; g_ccnt[n] = 0.f; g_t[n] = 0.f; }
}

// ---------------- stream-B kernel B: degrees ----------------
__global__ void __launch_bounds__(256)
k_deg(const int* __restrict__ ei) {
    int e = blockIdx.x * blockDim.x + threadIdx.x;
    if (e >= E_EDGES) return;
    atomicAdd(&g_rcnt[ei[e]], 1.f);
    atomicAdd(&g_ccnt[ei[E_EDGES + e]], 1.f);
}

// ---------------- stream-B kernel C: t accumulation ----------------
__global__ void __launch_bounds__(256)
k_edge2(const int* __restrict__ ei) {
    int e = blockIdx.x * blockDim.x + threadIdx.x;
    if (e >= E_EDGES) return;
    int row = ei[e];
    int col = ei[E_EDGES + e];
    float w = 1.f / fmaxf(g_ccnt[col], 1.f);
    atomicAdd(&g_t[row], w);
}

// ---------------- kernel 2: per-node h_i, P_r, P_c (fp16) + zero mN ----------------
__global__ void __launch_bounds__(256)
k_nodeP(const float* __restrict__ x,
        const float* __restrict__ Wn, const float* __restrict__ bn,
        const float* __restrict__ Wea, const float* __restrict__ bea) {
    __shared__ float Wns[IN_C * HID];
    __shared__ float Weas[64 * EDGE_D];
    __shared__ float bns[HID];
    __shared__ float base_s[EDGE_D];        // b_edge_agg + hG @ rows 80..95
    for (int t = threadIdx.x; t < IN_C * HID; t += blockDim.x) Wns[t] = Wn[t];
    for (int t = threadIdx.x; t < 64 * EDGE_D; t += blockDim.x) Weas[t] = Wea[t];
    if (threadIdx.x < HID) bns[threadIdx.x] = bn[threadIdx.x];
    if (threadIdx.x >= 32 && threadIdx.x < 32 + EDGE_D) {
        int j = threadIdx.x - 32;
        float b = bea[j];
        #pragma unroll
        for (int k = 0; k < GRAPH_D; k++)
            b += g_hG[k] * Wea[(80 + k) * EDGE_D + j];
        base_s[j] = b;
    }
    __syncthreads();

    int n = blockIdx.x * blockDim.x + threadIdx.x;
    if (n >= N_NODES) return;

    float4 z4 = make_float4(0.f, 0.f, 0.f, 0.f);
    float4* mz = reinterpret_cast<float4*>(g_mN + (size_t)n * EDGE_D);
    mz[0] = z4; mz[1] = z4; mz[2] = z4; mz[3] = z4;

    float acc[HID];
    #pragma unroll
    for (int j = 0; j < HID; j++) acc[j] = bns[j];
    const float4* xr = reinterpret_cast<const float4*>(x + (size_t)n * IN_C);
    #pragma unroll
    for (int k4 = 0; k4 < IN_C / 4; k4++) {
        float4 v = xr[k4];
        float vv[4] = {v.x, v.y, v.z, v.w};
        #pragma unroll
        for (int t = 0; t < 4; t++) {
            float xv = vv[t];
            int k = k4 * 4 + t;
            #pragma unroll
            for (int j = 0; j < HID; j++) acc[j] += xv * Wns[k * HID + j];
        }
    }
    float4* ho = reinterpret_cast<float4*>(g_hi + (size_t)n * HID);
    #pragma unroll
    for (int j4 = 0; j4 < HID / 4; j4++)
        ho[j4] = make_float4(acc[j4*4], acc[j4*4+1], acc[j4*4+2], acc[j4*4+3]);

    float pr[EDGE_D], pc[EDGE_D];
    #pragma unroll
    for (int j = 0; j < EDGE_D; j++) { pr[j] = base_s[j]; pc[j] = 0.f; }
    #pragma unroll
    for (int k = 0; k < HID; k++) {
        float v = acc[k];
        #pragma unroll
        for (int j = 0; j < EDGE_D; j++) {
            pr[j] += v * Weas[k * EDGE_D + j];
            pc[j] += v * Weas[(32 + k) * EDGE_D + j];
        }
    }
    // pack to fp16 and store as 2x 16B
    union { __half2 h2[8]; uint4 u4[2]; } pk, qk;
    #pragma unroll
    for (int j = 0; j < 8; j++) {
        pk.h2[j] = __floats2half2_rn(pr[2*j], pr[2*j+1]);
        qk.h2[j] = __floats2half2_rn(pc[2*j], pc[2*j+1]);
    }
    uint4* po = reinterpret_cast<uint4*>(g_Prh + (size_t)n * EDGE_D);
    uint4* qo = reinterpret_cast<uint4*>(g_Pch + (size_t)n * EDGE_D);
    po[0] = pk.u4[0]; po[1] = pk.u4[1];
    qo[0] = qk.u4[0]; qo[1] = qk.u4[1];
}

// ---------------- kernel 3: edge pass 1 — 4 threads/edge, fp16 gathers ----------------
// E_EDGES*4 is an exact multiple of 256 -> no tail.
__global__ void __launch_bounds__(256)
k_edge1(const int* __restrict__ ei,
        const float* __restrict__ edge_attr,
        const float* __restrict__ Wea) {
    __shared__ float Wc[EDGE_D * EDGE_D];   // rows 64..79 (edge_attr part)
    __shared__ float eas[256 * 4];          // staged edge_attr
    for (int t = threadIdx.x; t < EDGE_D * EDGE_D; t += blockDim.x)
        Wc[t] = Wea[64 * EDGE_D + t];
    __syncthreads();

    int t = blockIdx.x * blockDim.x + threadIdx.x;
    int e = t >> 2;
    int c = threadIdx.x & 3;

    int row = ei[e];
    int col = ei[E_EDGES + e];

    // fp16 gathers: 8B per lane, 32B per edge row (1 sector each)
    uint2 pru = reinterpret_cast<const uint2*>(g_Prh)[(size_t)row * 4 + c];
    uint2 pcu = reinterpret_cast<const uint2*>(g_Pch)[(size_t)col * 4 + c];
    __half2 pr01 = *reinterpret_cast<__half2*>(&pru.x);
    __half2 pr23 = *reinterpret_cast<__half2*>(&pru.y);
    __half2 pc01 = *reinterpret_cast<__half2*>(&pcu.x);
    __half2 pc23 = *reinterpret_cast<__half2*>(&pcu.y);
    float2 fr01 = __half22float2(pr01), fr23 = __half22float2(pr23);
    float2 fc01 = __half22float2(pc01), fc23 = __half22float2(pc23);

    float4 ea = *reinterpret_cast<const float4*>(edge_attr + (size_t)e * EDGE_D + c * 4);
    reinterpret_cast<float4*>(eas)[threadIdx.x] = ea;
    __syncwarp();
    const float4* eg = reinterpret_cast<const float4*>(eas + (threadIdx.x & ~3) * 4);

    float acc[4] = {fr01.x + fc01.x, fr01.y + fc01.y,
                    fr23.x + fc23.x, fr23.y + fc23.y};

    #pragma unroll
    for (int k4 = 0; k4 < 4; k4++) {
        float4 evv = eg[k4];
        float ev[4] = {evv.x, evv.y, evv.z, evv.w};
        #pragma unroll
        for (int kk = 0; kk < 4; kk++) {
            int k = k4 * 4 + kk;
            #pragma unroll
            for (int j = 0; j < 4; j++)
                acc[j] += ev[kk] * Wc[k * EDGE_D + c * 4 + j];
        }
    }
    red_add_f4(g_mN + (size_t)row * EDGE_D + c * 4,
               fmaxf(acc[0], 0.f), fmaxf(acc[1], 0.f),
               fmaxf(acc[2], 0.f), fmaxf(acc[3], 0.f));
}

// ---------------- kernel 5: node aggregator -> h_i2 ----------------
__global__ void __launch_bounds__(256)
k_node2(const float* __restrict__ Wna, const float* __restrict__ bna) {
    __shared__ float Wnas[48 * HID];
    __shared__ float base_s[HID];
    for (int t = threadIdx.x; t < 48 * HID; t += blockDim.x) Wnas[t] = Wna[t];
    if (threadIdx.x < HID) {
        float b = bna[threadIdx.x];
        #pragma unroll
        for (int k = 0; k < GRAPH_D; k++)
            b += g_hG[k] * Wna[(48 + k) * HID + threadIdx.x];
        base_s[threadIdx.x] = b;
    }
    __syncthreads();

    int n = blockIdx.x * blockDim.x + threadIdx.x;
    if (n >= N_NODES) return;

    float acc[HID];
    #pragma unroll
    for (int j = 0; j < HID; j++) acc[j] = base_s[j];

    const float4* hr = reinterpret_cast<const float4*>(g_hi + (size_t)n * HID);
    #pragma unroll
    for (int k4 = 0; k4 < HID / 4; k4++) {
        float4 v = hr[k4];
        float vv[4] = {v.x, v.y, v.z, v.w};
        #pragma unroll
        for (int t = 0; t < 4; t++) {
            float hv = vv[t];
            int k = k4 * 4 + t;
            #pragma unroll
            for (int j = 0; j < HID; j++) acc[j] += hv * Wnas[k * HID + j];
        }
    }
    float inv_c = 1.f / fmaxf(g_rcnt[n], 1.f);
    const float4* mp = reinterpret_cast<const float4*>(g_mN + (size_t)n * EDGE_D);
    #pragma unroll
    for (int k4 = 0; k4 < EDGE_D / 4; k4++) {
        float4 v = mp[k4];
        float vv[4] = {v.x, v.y, v.z, v.w};
        #pragma unroll
        for (int t = 0; t < 4; t++) {
            float mv = vv[t] * inv_c;
            int k = 32 + k4 * 4 + t;
            #pragma unroll
            for (int j = 0; j < HID; j++) acc[j] += mv * Wnas[k * HID + j];
        }
    }
    float4* h2 = reinterpret_cast<float4*>(g_h2 + (size_t)n * HID);
    #pragma unroll
    for (int j4 = 0; j4 < HID / 4; j4++)
        h2[j4] = make_float4(fmaxf(acc[j4*4], 0.f),   fmaxf(acc[j4*4+1], 0.f),
                             fmaxf(acc[j4*4+2], 0.f), fmaxf(acc[j4*4+3], 0.f));
}

// ---------------- kernel 6: reduce S0 = sum h_i2, S1 = sum t*h_i2 ----------------
__global__ void __launch_bounds__(256)
k_reduce() {
    int lane = threadIdx.x & 31;
    int warp = (blockIdx.x * blockDim.x + threadIdx.x) >> 5;
    int nwarps = (gridDim.x * blockDim.x) >> 5;

    float s0 = 0.f, s1 = 0.f;
    for (int n = warp; n < N_NODES; n += nwarps) {
        float h = g_h2[(size_t)n * HID + lane];
        float tv = g_t[n];
        s0 += h;
        s1 += tv * h;
    }
    atomicAdd(&g_S0[lane], s0);
    atomicAdd(&g_S1[lane], s1);
}

// ---------------- kernel 7: pooled linear + log_softmax ----------------
__global__ void k_final(const float* __restrict__ Wl, const float* __restrict__ bl,
                        const float* __restrict__ Wr, float* __restrict__ out) {
    __shared__ float p[OUT_C];
    int j = threadIdx.x;
    if (j < OUT_C) {
        float acc = 0.f;
        #pragma unroll
        for (int k = 0; k < HID; k++)
            acc += g_S1[k] * Wl[k * OUT_C + j] + g_S0[k] * Wr[k * OUT_C + j];
        p[j] = bl[j] + acc * (1.f / (float)N_NODES);
    }
    __syncthreads();
    if (j == 0) {
        float mx = -1e30f;
        #pragma unroll
        for (int i = 0; i < OUT_C; i++) mx = fmaxf(mx, p[i]);
        float se = 0.f;
        #pragma unroll
        for (int i = 0; i < OUT_C; i++) se += expf(p[i] - mx);
        float lse = mx + logf(se);
        #pragma unroll
        for (int i = 0; i < OUT_C; i++) out[i] = p[i] - lse;
    }
}

// ---------------- launch ----------------
extern "C" void kernel_launch(void* const* d_in, const int* in_sizes, int n_in,
                              void* d_out, int out_size) {
    const float* x          = (const float*)d_in[0];
    const float* edge_attr  = (const float*)d_in[1];
    const float* graph_attr = (const float*)d_in[2];
    const int*   edge_index = (const int*)  d_in[3];
    // d_in[4] = batch — unused
    const float* W_node     = (const float*)d_in[5];
    const float* b_node     = (const float*)d_in[6];
    const float* W_graph    = (const float*)d_in[7];
    const float* b_graph    = (const float*)d_in[8];
    const float* W_edge_agg = (const float*)d_in[9];
    const float* b_edge_agg = (const float*)d_in[10];
    const float* W_node_agg = (const float*)d_in[11];
    const float* b_node_agg = (const float*)d_in[12];
    const float* W_sage_l   = (const float*)d_in[13];
    const float* b_sage_l   = (const float*)d_in[14];
    const float* W_sage_r   = (const float*)d_in[15];
    float* out = (float*)d_out;

    static cudaStream_t sB = nullptr;
    static cudaEvent_t evFork = nullptr, evDeg = nullptr, evT = nullptr;
    if (sB == nullptr) {
        cudaStreamCreateWithFlags(&sB, cudaStreamNonBlocking);
        cudaEventCreateWithFlags(&evFork, cudaEventDisableTiming);
        cudaEventCreateWithFlags(&evDeg, cudaEventDisableTiming);
        cudaEventCreateWithFlags(&evT, cudaEventDisableTiming);
    }

    const int TB = 256;
    const int nodeBlocks  = (N_NODES + TB - 1) / TB;
    const int edge1Blocks = (E_EDGES * 4) / TB;
    const int edgeBlocks  = (E_EDGES + TB - 1) / TB;

    k_hG<<<1, 32>>>(graph_attr, W_graph, b_graph);

    // fork stream B: degrees + t, independent of Pr/Pc
    cudaEventRecord(evFork, 0);
    cudaStreamWaitEvent(sB, evFork, 0);
    k_zeroDeg<<<nodeBlocks, TB, 0, sB>>>();
    k_deg<<<edgeBlocks, TB, 0, sB>>>(edge_index);
    cudaEventRecord(evDeg, sB);
    k_edge2<<<edgeBlocks, TB, 0, sB>>>(edge_index);
    cudaEventRecord(evT, sB);

    // main stream
    k_nodeP<<<nodeBlocks, TB>>>(x, W_node, b_node, W_edge_agg, b_edge_agg);
    k_edge1<<<edge1Blocks, TB>>>(edge_index, edge_attr, W_edge_agg);

    cudaStreamWaitEvent(0, evDeg, 0);   // node2 needs rcnt
    k_node2<<<nodeBlocks, TB>>>(W_node_agg, b_node_agg);

    cudaStreamWaitEvent(0, evT, 0);     // reduce needs t
    k_reduce<<<128, TB>>>();
    k_final<<<1, 32>>>(W_sage_l, b_sage_l, W_sage_r, out);
}

// round 8
// speedup vs baseline: 1.0366x; 1.0366x over previous
#include <cuda_runtime.h>
#include <cuda_fp16.h>

#define N_NODES 100000
#define E_EDGES 1600000
#define IN_C    32
#define HID     32
#define OUT_C   8
#define EDGE_D  16
#define GRAPH_D 16

// ---------------- device scratch ----------------
__device__ float g_hi [N_NODES * HID];
__device__ uint4 g_Prh[N_NODES * 2];        // fp16 P_r rows (32B each), bias+hG folded
__device__ uint4 g_Pch[N_NODES * 2];        // fp16 P_c rows
__device__ uint4 g_mNh[N_NODES * 2];        // fp16 mN accumulator rows (32B each)
__device__ float g_h2 [N_NODES * HID];
__device__ float g_t  [N_NODES];            // sum over out-edges of 1/ccnt[col]
__device__ float g_rcnt[N_NODES];
__device__ float g_ccnt[N_NODES];
__device__ float g_hG [GRAPH_D];
__device__ float g_S0 [HID];
__device__ float g_S1 [HID];

__device__ __forceinline__ void red_add_v4h2(void* addr, unsigned a, unsigned b,
                                             unsigned c, unsigned d) {
    asm volatile("red.global.add.noftz.v4.f16x2 [%0], {%1,%2,%3,%4};"
                 :: "l"(addr), "r"(a), "r"(b), "r"(c), "r"(d) : "memory");
}

// ---------------- kernel: graph embedding + zero S0/S1 ----------------
__global__ void k_hG(const float* __restrict__ ga, const float* __restrict__ Wg,
                     const float* __restrict__ bg) {
    int j = threadIdx.x;
    if (j < GRAPH_D) {
        float acc = bg[j];
        #pragma unroll
        for (int k = 0; k < GRAPH_D; k++) acc += ga[k] * Wg[k * GRAPH_D + j];
        g_hG[j] = acc;
    }
    if (j < HID) { g_S0[j] = 0.f; g_S1[j] = 0.f; }
}

// ---------------- stream-B: zero degrees, then degrees ----------------
__global__ void __launch_bounds__(256)
k_zeroDeg() {
    int n = blockIdx.x * blockDim.x + threadIdx.x;
    if (n < N_NODES) { g_rcnt[n] = 0.f; g_ccnt[n] = 0.f; g_t[n] = 0.f; }
}

__global__ void __launch_bounds__(256)
k_deg(const int* __restrict__ ei) {
    int e = blockIdx.x * blockDim.x + threadIdx.x;
    if (e >= E_EDGES) return;
    atomicAdd(&g_rcnt[ei[e]], 1.f);
    atomicAdd(&g_ccnt[ei[E_EDGES + e]], 1.f);
}

// ---------------- stream-B: t accumulation (runs after edge1, beside node2) ----------------
__global__ void __launch_bounds__(256)
k_edge2(const int* __restrict__ ei) {
    int e = blockIdx.x * blockDim.x + threadIdx.x;
    if (e >= E_EDGES) return;
    int row = ei[e];
    int col = ei[E_EDGES + e];
    float w = 1.f / fmaxf(g_ccnt[col], 1.f);
    atomicAdd(&g_t[row], w);
}

// ---------------- kernel: per-node h_i, P_r, P_c (fp16) + zero mN ----------------
__global__ void __launch_bounds__(256)
k_nodeP(const float* __restrict__ x,
        const float* __restrict__ Wn, const float* __restrict__ bn,
        const float* __restrict__ Wea, const float* __restrict__ bea) {
    __shared__ float Wns[IN_C * HID];
    __shared__ float Weas[64 * EDGE_D];
    __shared__ float bns[HID];
    __shared__ float base_s[EDGE_D];        // b_edge_agg + hG @ rows 80..95
    for (int t = threadIdx.x; t < IN_C * HID; t += blockDim.x) Wns[t] = Wn[t];
    for (int t = threadIdx.x; t < 64 * EDGE_D; t += blockDim.x) Weas[t] = Wea[t];
    if (threadIdx.x < HID) bns[threadIdx.x] = bn[threadIdx.x];
    if (threadIdx.x >= 32 && threadIdx.x < 32 + EDGE_D) {
        int j = threadIdx.x - 32;
        float b = bea[j];
        #pragma unroll
        for (int k = 0; k < GRAPH_D; k++)
            b += g_hG[k] * Wea[(80 + k) * EDGE_D + j];
        base_s[j] = b;
    }
    __syncthreads();

    int n = blockIdx.x * blockDim.x + threadIdx.x;
    if (n >= N_NODES) return;

    uint4 z4 = make_uint4(0u, 0u, 0u, 0u);
    g_mNh[n * 2 + 0] = z4;
    g_mNh[n * 2 + 1] = z4;

    float acc[HID];
    #pragma unroll
    for (int j = 0; j < HID; j++) acc[j] = bns[j];
    const float4* xr = reinterpret_cast<const float4*>(x + (size_t)n * IN_C);
    #pragma unroll
    for (int k4 = 0; k4 < IN_C / 4; k4++) {
        float4 v = xr[k4];
        float vv[4] = {v.x, v.y, v.z, v.w};
        #pragma unroll
        for (int t = 0; t < 4; t++) {
            float xv = vv[t];
            int k = k4 * 4 + t;
            #pragma unroll
            for (int j = 0; j < HID; j++) acc[j] += xv * Wns[k * HID + j];
        }
    }
    float4* ho = reinterpret_cast<float4*>(g_hi + (size_t)n * HID);
    #pragma unroll
    for (int j4 = 0; j4 < HID / 4; j4++)
        ho[j4] = make_float4(acc[j4*4], acc[j4*4+1], acc[j4*4+2], acc[j4*4+3]);

    float pr[EDGE_D], pc[EDGE_D];
    #pragma unroll
    for (int j = 0; j < EDGE_D; j++) { pr[j] = base_s[j]; pc[j] = 0.f; }
    #pragma unroll
    for (int k = 0; k < HID; k++) {
        float v = acc[k];
        #pragma unroll
        for (int j = 0; j < EDGE_D; j++) {
            pr[j] += v * Weas[k * EDGE_D + j];
            pc[j] += v * Weas[(32 + k) * EDGE_D + j];
        }
    }
    union { __half2 h2[8]; uint4 u4[2]; } pk, qk;
    #pragma unroll
    for (int j = 0; j < 8; j++) {
        pk.h2[j] = __floats2half2_rn(pr[2*j], pr[2*j+1]);
        qk.h2[j] = __floats2half2_rn(pc[2*j], pc[2*j+1]);
    }
    g_Prh[n * 2 + 0] = pk.u4[0];
    g_Prh[n * 2 + 1] = pk.u4[1];
    g_Pch[n * 2 + 0] = qk.u4[0];
    g_Pch[n * 2 + 1] = qk.u4[1];
}

// ---------------- kernel: edge pass 1 — 4 threads/edge, fp16 in + fp16 red out ----------------
// E_EDGES*4 is an exact multiple of 256 -> no tail.
__global__ void __launch_bounds__(256)
k_edge1(const int* __restrict__ ei,
        const float* __restrict__ edge_attr,
        const float* __restrict__ Wea) {
    __shared__ float Wc[EDGE_D * EDGE_D];   // rows 64..79 (edge_attr part)
    __shared__ float eas[256 * 4];          // staged edge_attr
    for (int t = threadIdx.x; t < EDGE_D * EDGE_D; t += blockDim.x)
        Wc[t] = Wea[64 * EDGE_D + t];
    __syncthreads();

    int t = blockIdx.x * blockDim.x + threadIdx.x;
    int e = t >> 2;
    int c = threadIdx.x & 3;

    int row = ei[e];
    int col = ei[E_EDGES + e];

    // fp16 gathers: 8B per lane, 32B per edge row (1 sector per row)
    uint2 pru = reinterpret_cast<const uint2*>(g_Prh)[(size_t)row * 4 + c];
    uint2 pcu = reinterpret_cast<const uint2*>(g_Pch)[(size_t)col * 4 + c];
    float2 fr01 = __half22float2(*reinterpret_cast<__half2*>(&pru.x));
    float2 fr23 = __half22float2(*reinterpret_cast<__half2*>(&pru.y));
    float2 fc01 = __half22float2(*reinterpret_cast<__half2*>(&pcu.x));
    float2 fc23 = __half22float2(*reinterpret_cast<__half2*>(&pcu.y));

    float4 ea = *reinterpret_cast<const float4*>(edge_attr + (size_t)e * EDGE_D + c * 4);
    reinterpret_cast<float4*>(eas)[threadIdx.x] = ea;
    __syncwarp();
    const float4* eg = reinterpret_cast<const float4*>(eas + (threadIdx.x & ~3) * 4);

    float acc[4] = {fr01.x + fc01.x, fr01.y + fc01.y,
                    fr23.x + fc23.x, fr23.y + fc23.y};

    #pragma unroll
    for (int k4 = 0; k4 < 4; k4++) {
        float4 evv = eg[k4];
        float ev[4] = {evv.x, evv.y, evv.z, evv.w};
        #pragma unroll
        for (int kk = 0; kk < 4; kk++) {
            int k = k4 * 4 + kk;
            #pragma unroll
            for (int j = 0; j < 4; j++)
                acc[j] += ev[kk] * Wc[k * EDGE_D + c * 4 + j];
        }
    }
    // relu, pack to f16x2, pair-exchange, even lanes issue one 16B red each
    __half2 ha = __floats2half2_rn(fmaxf(acc[0], 0.f), fmaxf(acc[1], 0.f));
    __half2 hb = __floats2half2_rn(fmaxf(acc[2], 0.f), fmaxf(acc[3], 0.f));
    unsigned a0 = *reinterpret_cast<unsigned*>(&ha);
    unsigned a1 = *reinterpret_cast<unsigned*>(&hb);
    unsigned b0 = __shfl_xor_sync(0xFFFFFFFFu, a0, 1, 4);
    unsigned b1 = __shfl_xor_sync(0xFFFFFFFFu, a1, 1, 4);
    if ((c & 1) == 0) {
        // lane 0 covers halves 0..7, lane 2 covers halves 8..15
        __half* base = reinterpret_cast<__half*>(g_mNh + (size_t)row * 2) + (c >> 1) * 8;
        red_add_v4h2(base, a0, a1, b0, b1);
    }
}

// ---------------- kernel: node aggregator -> h_i2 ----------------
__global__ void __launch_bounds__(256)
k_node2(const float* __restrict__ Wna, const float* __restrict__ bna) {
    __shared__ float Wnas[48 * HID];
    __shared__ float base_s[HID];
    for (int t = threadIdx.x; t < 48 * HID; t += blockDim.x) Wnas[t] = Wna[t];
    if (threadIdx.x < HID) {
        float b = bna[threadIdx.x];
        #pragma unroll
        for (int k = 0; k < GRAPH_D; k++)
            b += g_hG[k] * Wna[(48 + k) * HID + threadIdx.x];
        base_s[threadIdx.x] = b;
    }
    __syncthreads();

    int n = blockIdx.x * blockDim.x + threadIdx.x;
    if (n >= N_NODES) return;

    float acc[HID];
    #pragma unroll
    for (int j = 0; j < HID; j++) acc[j] = base_s[j];

    const float4* hr = reinterpret_cast<const float4*>(g_hi + (size_t)n * HID);
    #pragma unroll
    for (int k4 = 0; k4 < HID / 4; k4++) {
        float4 v = hr[k4];
        float vv[4] = {v.x, v.y, v.z, v.w};
        #pragma unroll
        for (int t = 0; t < 4; t++) {
            float hv = vv[t];
            int k = k4 * 4 + t;
            #pragma unroll
            for (int j = 0; j < HID; j++) acc[j] += hv * Wnas[k * HID + j];
        }
    }
    float inv_c = 1.f / fmaxf(g_rcnt[n], 1.f);
    // unpack fp16 mN row (32B)
    union { uint4 u4[2]; __half2 h2[8]; } mu;
    mu.u4[0] = g_mNh[n * 2 + 0];
    mu.u4[1] = g_mNh[n * 2 + 1];
    #pragma unroll
    for (int p = 0; p < 8; p++) {
        float2 mf = __half22float2(mu.h2[p]);
        float m0 = mf.x * inv_c;
        float m1 = mf.y * inv_c;
        int k0 = 32 + 2 * p;
        #pragma unroll
        for (int j = 0; j < HID; j++) {
            acc[j] += m0 * Wnas[k0 * HID + j];
            acc[j] += m1 * Wnas[(k0 + 1) * HID + j];
        }
    }
    float4* h2 = reinterpret_cast<float4*>(g_h2 + (size_t)n * HID);
    #pragma unroll
    for (int j4 = 0; j4 < HID / 4; j4++)
        h2[j4] = make_float4(fmaxf(acc[j4*4], 0.f),   fmaxf(acc[j4*4+1], 0.f),
                             fmaxf(acc[j4*4+2], 0.f), fmaxf(acc[j4*4+3], 0.f));
}

// ---------------- kernel: reduce S0 = sum h_i2, S1 = sum t*h_i2 ----------------
__global__ void __launch_bounds__(256)
k_reduce() {
    int lane = threadIdx.x & 31;
    int warp = (blockIdx.x * blockDim.x + threadIdx.x) >> 5;
    int nwarps = (gridDim.x * blockDim.x) >> 5;

    float s0 = 0.f, s1 = 0.f;
    for (int n = warp; n < N_NODES; n += nwarps) {
        float h = g_h2[(size_t)n * HID + lane];
        float tv = g_t[n];
        s0 += h;
        s1 += tv * h;
    }
    atomicAdd(&g_S0[lane], s0);
    atomicAdd(&g_S1[lane], s1);
}

// ---------------- kernel: pooled linear + log_softmax ----------------
__global__ void k_final(const float* __restrict__ Wl, const float* __restrict__ bl,
                        const float* __restrict__ Wr, float* __restrict__ out) {
    __shared__ float p[OUT_C];
    int j = threadIdx.x;
    if (j < OUT_C) {
        float acc = 0.f;
        #pragma unroll
        for (int k = 0; k < HID; k++)
            acc += g_S1[k] * Wl[k * OUT_C + j] + g_S0[k] * Wr[k * OUT_C + j];
        p[j] = bl[j] + acc * (1.f / (float)N_NODES);
    }
    __syncthreads();
    if (j == 0) {
        float mx = -1e30f;
        #pragma unroll
        for (int i = 0; i < OUT_C; i++) mx = fmaxf(mx, p[i]);
        float se = 0.f;
        #pragma unroll
        for (int i = 0; i < OUT_C; i++) se += expf(p[i] - mx);
        float lse = mx + logf(se);
        #pragma unroll
        for (int i = 0; i < OUT_C; i++) out[i] = p[i] - lse;
    }
}

// ---------------- launch ----------------
extern "C" void kernel_launch(void* const* d_in, const int* in_sizes, int n_in,
                              void* d_out, int out_size) {
    const float* x          = (const float*)d_in[0];
    const float* edge_attr  = (const float*)d_in[1];
    const float* graph_attr = (const float*)d_in[2];
    const int*   edge_index = (const int*)  d_in[3];
    // d_in[4] = batch — unused
    const float* W_node     = (const float*)d_in[5];
    const float* b_node     = (const float*)d_in[6];
    const float* W_graph    = (const float*)d_in[7];
    const float* b_graph    = (const float*)d_in[8];
    const float* W_edge_agg = (const float*)d_in[9];
    const float* b_edge_agg = (const float*)d_in[10];
    const float* W_node_agg = (const float*)d_in[11];
    const float* b_node_agg = (const float*)d_in[12];
    const float* W_sage_l   = (const float*)d_in[13];
    const float* b_sage_l   = (const float*)d_in[14];
    const float* W_sage_r   = (const float*)d_in[15];
    float* out = (float*)d_out;

    static cudaStream_t sB = nullptr;
    static cudaEvent_t evFork = nullptr, evDeg = nullptr, evE1 = nullptr, evT = nullptr;
    if (sB == nullptr) {
        cudaStreamCreateWithFlags(&sB, cudaStreamNonBlocking);
        cudaEventCreateWithFlags(&evFork, cudaEventDisableTiming);
        cudaEventCreateWithFlags(&evDeg, cudaEventDisableTiming);
        cudaEventCreateWithFlags(&evE1, cudaEventDisableTiming);
        cudaEventCreateWithFlags(&evT, cudaEventDisableTiming);
    }

    const int TB = 256;
    const int nodeBlocks  = (N_NODES + TB - 1) / TB;
    const int edge1Blocks = (E_EDGES * 4) / TB;
    const int edgeBlocks  = (E_EDGES + TB - 1) / TB;

    k_hG<<<1, 32>>>(graph_attr, W_graph, b_graph);

    // stream B: degrees, overlapped ONLY with compute-bound k_nodeP
    cudaEventRecord(evFork, 0);
    cudaStreamWaitEvent(sB, evFork, 0);
    k_zeroDeg<<<nodeBlocks, TB, 0, sB>>>();
    k_deg<<<edgeBlocks, TB, 0, sB>>>(edge_index);
    cudaEventRecord(evDeg, sB);

    // main stream
    k_nodeP<<<nodeBlocks, TB>>>(x, W_node, b_node, W_edge_agg, b_edge_agg);
    cudaStreamWaitEvent(0, evDeg, 0);   // keep deg traffic out of edge1's window
    k_edge1<<<edge1Blocks, TB>>>(edge_index, edge_attr, W_edge_agg);
    cudaEventRecord(evE1, 0);

    // stream B: t accumulation, overlapped with node2
    cudaStreamWaitEvent(sB, evE1, 0);
    k_edge2<<<edgeBlocks, TB, 0, sB>>>(edge_index);
    cudaEventRecord(evT, sB);

    k_node2<<<nodeBlocks, TB>>>(W_node_agg, b_node_agg);

    cudaStreamWaitEvent(0, evT, 0);
    k_reduce<<<128, TB>>>();
    k_final<<<1, 32>>>(W_sage_l, b_sage_l, W_sage_r, out);
}